// round 13
// baseline (speedup 1.0000x reference)
#include <cuda_runtime.h>
#include <cuda_fp16.h>
#include <cstdint>

#define N_NODES 100000
#define N_EDGES 1600000
#define N_GRAPHS 2048
#define D 128
#define DFC 256
#define DOUT 8

#define SCAN_CHUNK 1024
#define SCAN_NB ((N_NODES + SCAN_CHUNK - 1) / SCAN_CHUNK)   // 98

#define SA 20     // A smem stride (floats): banks (20g+t)%32 all distinct
#define SB 136    // B smem stride (floats): banks (8t+g)%32 all distinct

// ---------------- scratch (static device globals; no allocation) ----------------
__device__ float  g_agg[(size_t)N_NODES * D];
__device__ float  g_hA[(size_t)N_NODES * D];
__device__ float  g_hB[(size_t)N_NODES * D];
__device__ __half g_x16[(size_t)N_NODES * D];
__device__ __half g_h16A[(size_t)N_NODES * D];
__device__ __half g_h16B[(size_t)N_NODES * D];
__device__ float  g_pool[(size_t)N_GRAPHS * D];
__device__ float  g_fc1[(size_t)N_GRAPHS * DFC];
__device__ int    g_src[N_EDGES];
__device__ int    g_dst[N_EDGES];
__device__ int    g_batch[N_NODES];
__device__ int    g_counts[N_NODES];          // zeroed by cudaMemsetAsync
__device__ int    g_row_ptr[N_NODES + 1];
__device__ int    g_cursor[N_NODES];
__device__ int    g_csr_src[N_EDGES];
__device__ int    g_blocksum[SCAN_NB];
__device__ unsigned g_gbar;                   // zeroed by cudaMemsetAsync

__device__ __forceinline__ const float* pick_in(const float* x, int sel) {
    return sel == 0 ? x : (sel == 1 ? g_hA : g_hB);
}
__device__ __forceinline__ float* pick_out(int sel) {
    return sel == 1 ? g_hA : g_hB;
}
__device__ __forceinline__ const __half* pick_in16(int sel) {
    return sel == 0 ? g_x16 : (sel == 1 ? g_h16A : g_h16B);
}
__device__ __forceinline__ __half* pick_out16(int sel) {
    return sel == 1 ? g_h16A : g_h16B;
}

// ---------------- tf32 helpers ----------------
__device__ __forceinline__ uint32_t f2tf32(float v) {
    uint32_t r;
    asm("cvt.rna.tf32.f32 %0, %1;" : "=r"(r) : "f"(v));
    return r;
}

__device__ __forceinline__ void mma_tf32(float* c, const uint32_t* a,
                                         uint32_t b0, uint32_t b1) {
    asm("mma.sync.aligned.m16n8k8.row.col.f32.tf32.tf32.f32 "
        "{%0,%1,%2,%3},{%4,%5,%6,%7},{%8,%9},{%0,%1,%2,%3};"
        : "+f"(c[0]), "+f"(c[1]), "+f"(c[2]), "+f"(c[3])
        : "r"(a[0]), "r"(a[1]), "r"(a[2]), "r"(a[3]), "r"(b0), "r"(b1));
}

// ---------------- software grid barrier (blocks guaranteed co-resident) ------
__device__ __forceinline__ void grid_bar(unsigned target) {
    __syncthreads();
    if (threadIdx.x == 0) {
        __threadfence();
        atomicAdd(&g_gbar, 1u);
        while (*(volatile unsigned*)&g_gbar < target) { }
        __threadfence();
    }
    __syncthreads();
}

// ---------------- convert indices (self-detecting dtype) + per-dst counts ----------------
__device__ __forceinline__ int detect_is64(const void* ei) {
    const long long* p64 = (const long long*)ei;
    int ok = 1;
    #pragma unroll
    for (int i = 0; i < 16; i++) {
        long long v = __ldg(&p64[i]);
        if (v < 0 || v >= N_NODES) ok = 0;
    }
    return ok;
}

__global__ void convert_count_kernel(const void* ei, const void* batch) {
    int i = blockIdx.x * blockDim.x + threadIdx.x;
    int is64 = detect_is64(ei);
    if (i < N_EDGES) {
        int s, d;
        if (is64) {
            const long long* p = (const long long*)ei;
            s = (int)__ldg(&p[i]);
            d = (int)__ldg(&p[(size_t)N_EDGES + i]);
        } else {
            const int* p = (const int*)ei;
            s = __ldg(&p[i]);
            d = __ldg(&p[N_EDGES + i]);
        }
        g_src[i] = s;
        g_dst[i] = d;
        atomicAdd(&g_counts[d], 1);
    }
    if (i < N_NODES) {
        if (is64) g_batch[i] = (int)__ldg(&((const long long*)batch)[i]);
        else      g_batch[i] = __ldg(&((const int*)batch)[i]);
    }
}

// ---------------- fused CSR build: scan1 + scan2 + scan3 + fill, one kernel ------
// 98 blocks x 256 threads; software grid barriers between phases.
__global__ __launch_bounds__(256) void csr_build_kernel() {
    int b = blockIdx.x, t = threadIdx.x;

    // ---- phase 1: per-chunk totals (old scan1) ----
    {
        __shared__ int sh[256];
        int i0 = b * SCAN_CHUNK + t * 4;
        int s = 0;
        #pragma unroll
        for (int j = 0; j < 4; j++) {
            int i = i0 + j;
            if (i < N_NODES) s += g_counts[i];
        }
        sh[t] = s;
        __syncthreads();
        for (int off = 128; off > 0; off >>= 1) {
            if (t < off) sh[t] += sh[t + off];
            __syncthreads();
        }
        if (t == 0) g_blocksum[b] = sh[0];
    }

    grid_bar(SCAN_NB);          // all blocksums visible

    // ---- phase 2: each block redundantly scans the 98 chunk sums, then its chunk ----
    {
        __shared__ int pre[128];
        int v = (t < SCAN_NB && t < 128) ? g_blocksum[t] : 0;
        if (t < 128) pre[t] = v;
        __syncthreads();
        #pragma unroll
        for (int off = 1; off < 128; off <<= 1) {
            int u = 0;
            if (t < 128 && t >= off) u = pre[t - off];
            __syncthreads();
            if (t < 128) pre[t] += u;
            __syncthreads();
        }
        __shared__ int myblockbase;
        if (t == 0) myblockbase = (b == 0) ? 0 : pre[b - 1];
        __syncthreads();

        __shared__ int sh[256];
        int i0 = b * SCAN_CHUNK + t * 4;
        int c[4];
        int tsum = 0;
        #pragma unroll
        for (int j = 0; j < 4; j++) {
            int i = i0 + j;
            c[j] = (i < N_NODES) ? g_counts[i] : 0;
            tsum += c[j];
        }
        sh[t] = tsum;
        __syncthreads();
        #pragma unroll
        for (int off = 1; off < 256; off <<= 1) {
            int v2 = (t >= off) ? sh[t - off] : 0;
            __syncthreads();
            sh[t] += v2;
            __syncthreads();
        }
        int base = myblockbase + sh[t] - tsum;
        #pragma unroll
        for (int j = 0; j < 4; j++) {
            int i = i0 + j;
            if (i < N_NODES) {
                g_row_ptr[i] = base;
                g_cursor[i]  = base;
                base += c[j];
            }
        }
        if (b == SCAN_NB - 1 && t == 0) g_row_ptr[N_NODES] = N_EDGES;
    }

    grid_bar(2 * SCAN_NB);      // all cursors initialized

    // ---- phase 3: fill CSR (grid-stride over edges) ----
    {
        int nthr = SCAN_NB * 256;
        for (int e = b * 256 + t; e < N_EDGES; e += nthr) {
            int d = g_dst[e];
            int pos = atomicAdd(&g_cursor[d], 1);
            g_csr_src[pos] = g_src[e];
        }
    }
}

// ---------------- x -> fp16 mirror ----------------
__global__ void convert_x16_kernel(const float* __restrict__ x) {
    int i = blockIdx.x * blockDim.x + threadIdx.x;
    if (i >= N_NODES * (D / 4)) return;
    float4 v = __ldg(reinterpret_cast<const float4*>(x) + i);
    __half2 h0 = __floats2half2_rn(v.x, v.y);
    __half2 h1 = __floats2half2_rn(v.z, v.w);
    uint2 u;
    u.x = *reinterpret_cast<uint32_t*>(&h0);
    u.y = *reinterpret_cast<uint32_t*>(&h1);
    reinterpret_cast<uint2*>(g_x16)[i] = u;
}

// ---------------- gather: shfl-broadcast indices, 8-deep MLP ----------------
__device__ __forceinline__ void acc_h4(float4& acc, uint2 u) {
    __half2 p0 = *reinterpret_cast<const __half2*>(&u.x);
    __half2 p1 = *reinterpret_cast<const __half2*>(&u.y);
    float2 a = __half22float2(p0);
    float2 b = __half22float2(p1);
    acc.x += a.x; acc.y += a.y; acc.z += b.x; acc.w += b.y;
}

__global__ void gather_kernel(int sel_in) {
    long long idx = (long long)blockIdx.x * blockDim.x + threadIdx.x;
    int node = (int)(idx >> 5);
    if (node >= N_NODES) return;
    int lane = (int)(idx & 31);
    const __half* h = pick_in16(sel_in);
    const uint2* h8 = reinterpret_cast<const uint2*>(h);
    int beg = g_row_ptr[node];
    int end = g_row_ptr[node + 1];
    int deg = end - beg;

    // cooperative index prefetch: one coalesced load covers up to 32 edges
    int myidx = 0;
    if (lane < deg) myidx = __ldg(&g_csr_src[beg + lane]);

    float4 acc = make_float4(0.f, 0.f, 0.f, 0.f);
    int n32 = deg < 32 ? deg : 32;

    #pragma unroll 8
    for (int j = 0; j < n32; j++) {
        int s = __shfl_sync(0xffffffffu, myidx, j);
        uint2 u = __ldg(&h8[(size_t)s * 32 + lane]);
        acc_h4(acc, u);
    }
    // rare tail: deg > 32
    for (int e = beg + 32; e < end; e++) {
        int s = __ldg(&g_csr_src[e]);
        uint2 u = __ldg(&h8[(size_t)s * 32 + lane]);
        acc_h4(acc, u);
    }
    reinterpret_cast<float4*>(g_agg)[(size_t)node * 32 + lane] = acc;
}

// ---------------- fused dual-GEMM via tf32 mma.sync ----------------
__device__ __forceinline__ void mma_pair(
    const uint32_t* __restrict__ As_, const uint32_t* __restrict__ Bs_,
    int kc, int warp_m, int warp_n, int g, int t, float acc[2][8][4])
{
    uint32_t afr[2][4];
    #pragma unroll
    for (int mt = 0; mt < 2; mt++) {
        int r0 = warp_m * 32 + mt * 16;
        afr[mt][0] = As_[(r0 + g) * SA + kc + t];
        afr[mt][1] = As_[(r0 + g + 8) * SA + kc + t];
        afr[mt][2] = As_[(r0 + g) * SA + kc + t + 4];
        afr[mt][3] = As_[(r0 + g + 8) * SA + kc + t + 4];
    }
    #pragma unroll
    for (int nt = 0; nt < 8; nt++) {
        int n0 = warp_n * 64 + nt * 8;
        uint32_t b0 = Bs_[(kc + t) * SB + n0 + g];
        uint32_t b1 = Bs_[(kc + t + 4) * SB + n0 + g];
        mma_tf32(acc[0][nt], afr[0], b0, b1);
        mma_tf32(acc[1][nt], afr[1], b0, b1);
    }
}

__global__ __launch_bounds__(256) void gemm_fused_kernel(
    const float* __restrict__ x, int sel_in, int sel_out,
    const float* __restrict__ Wrel, const float* __restrict__ Wroot,
    const float* __restrict__ bias)
{
    __shared__ uint32_t Aa[128 * SA];
    __shared__ uint32_t Ah[128 * SA];
    __shared__ uint32_t Br[16 * SB];
    __shared__ uint32_t Bo[16 * SB];

    const float* hin = pick_in(x, sel_in);
    float* hout = pick_out(sel_out);
    __half* hout16 = pick_out16(sel_out);

    int m0 = blockIdx.x * 128;
    int tid = threadIdx.x;
    int wid = tid >> 5;
    int lane = tid & 31;
    int warp_m = wid & 3;
    int warp_n = wid >> 2;
    int g = lane >> 2;
    int t = lane & 3;

    float acc[2][8][4];
    #pragma unroll
    for (int mt = 0; mt < 2; mt++)
        #pragma unroll
        for (int nt = 0; nt < 8; nt++)
            #pragma unroll
            for (int j = 0; j < 4; j++) acc[mt][nt][j] = 0.f;

    for (int k0 = 0; k0 < 128; k0 += 16) {
        #pragma unroll
        for (int i = 0; i < 2; i++) {
            int f = tid * 2 + i;
            int row = f >> 2;
            int c4 = f & 3;
            int gr = m0 + row;
            float4 va = make_float4(0.f, 0.f, 0.f, 0.f);
            float4 vh = make_float4(0.f, 0.f, 0.f, 0.f);
            if (gr < N_NODES) {
                va = *reinterpret_cast<const float4*>(g_agg + (size_t)gr * 128 + k0 + c4 * 4);
                vh = *reinterpret_cast<const float4*>(hin   + (size_t)gr * 128 + k0 + c4 * 4);
            }
            int base = row * SA + c4 * 4;
            Aa[base + 0] = f2tf32(va.x); Aa[base + 1] = f2tf32(va.y);
            Aa[base + 2] = f2tf32(va.z); Aa[base + 3] = f2tf32(va.w);
            Ah[base + 0] = f2tf32(vh.x); Ah[base + 1] = f2tf32(vh.y);
            Ah[base + 2] = f2tf32(vh.z); Ah[base + 3] = f2tf32(vh.w);
        }
        #pragma unroll
        for (int i = 0; i < 2; i++) {
            int f = tid * 2 + i;
            int kr = f >> 5;
            int c4 = f & 31;
            float4 vr = *reinterpret_cast<const float4*>(Wrel  + (size_t)(k0 + kr) * 128 + c4 * 4);
            float4 vo = *reinterpret_cast<const float4*>(Wroot + (size_t)(k0 + kr) * 128 + c4 * 4);
            int base = kr * SB + c4 * 4;
            Br[base + 0] = f2tf32(vr.x); Br[base + 1] = f2tf32(vr.y);
            Br[base + 2] = f2tf32(vr.z); Br[base + 3] = f2tf32(vr.w);
            Bo[base + 0] = f2tf32(vo.x); Bo[base + 1] = f2tf32(vo.y);
            Bo[base + 2] = f2tf32(vo.z); Bo[base + 3] = f2tf32(vo.w);
        }
        __syncthreads();

        #pragma unroll
        for (int kc = 0; kc < 16; kc += 8) {
            mma_pair(Aa, Br, kc, warp_m, warp_n, g, t, acc);
            mma_pair(Ah, Bo, kc, warp_m, warp_n, g, t, acc);
        }
        __syncthreads();
    }

    #pragma unroll
    for (int nt = 0; nt < 8; nt++) {
        int col = warp_n * 64 + nt * 8 + 2 * t;
        float b0 = __ldg(&bias[col]);
        float b1 = __ldg(&bias[col + 1]);
        #pragma unroll
        for (int mt = 0; mt < 2; mt++) {
            int row0 = m0 + warp_m * 32 + mt * 16 + g;
            if (row0 < N_NODES) {
                float lo = fmaxf(acc[mt][nt][0] + b0, 0.f);
                float hi = fmaxf(acc[mt][nt][1] + b1, 0.f);
                *reinterpret_cast<float2*>(&hout[(size_t)row0 * 128 + col]) =
                    make_float2(lo, hi);
                *reinterpret_cast<__half2*>(&hout16[(size_t)row0 * 128 + col]) =
                    __floats2half2_rn(lo, hi);
            }
            int row1 = row0 + 8;
            if (row1 < N_NODES) {
                float lo = fmaxf(acc[mt][nt][2] + b0, 0.f);
                float hi = fmaxf(acc[mt][nt][3] + b1, 0.f);
                *reinterpret_cast<float2*>(&hout[(size_t)row1 * 128 + col]) =
                    make_float2(lo, hi);
                *reinterpret_cast<__half2*>(&hout16[(size_t)row1 * 128 + col]) =
                    __floats2half2_rn(lo, hi);
            }
        }
    }
}

// ---------------- pool: sorted-batch segments, block per graph, no atomics ----------------
__device__ __forceinline__ int lower_bound_batch(int v) {
    int lo = 0, hi = N_NODES;
    while (lo < hi) {
        int m = (lo + hi) >> 1;
        if (g_batch[m] < v) lo = m + 1; else hi = m;
    }
    return lo;
}

__global__ __launch_bounds__(128) void pool_kernel(const float* __restrict__ x, int sel_in) {
    int g = blockIdx.x;
    int t = threadIdx.x;
    const float* h = pick_in(x, sel_in);
    int lo = lower_bound_batch(g);
    int hi = lower_bound_batch(g + 1);
    float acc = 0.f;
    for (int n = lo; n < hi; n++)
        acc += __ldg(&h[(size_t)n * 128 + t]);
    float cnt = (float)(hi - lo);
    g_pool[(size_t)g * 128 + t] = acc / fmaxf(cnt, 1.0f);
}

// ---------------- fc1: 4 graphs per block ----------------
__global__ __launch_bounds__(256) void fc1_kernel(
    const float* __restrict__ w, const float* __restrict__ b)
{
    __shared__ float p[4][128];
    int g0 = blockIdx.x * 4;
    int t = threadIdx.x;
    #pragma unroll
    for (int i = 0; i < 2; i++) {
        int f = t + i * 256;
        p[f >> 7][f & 127] = g_pool[(size_t)g0 * 128 + f];
    }
    __syncthreads();
    float acc0 = b[t], acc1 = b[t], acc2 = b[t], acc3 = b[t];
    #pragma unroll 4
    for (int k = 0; k < 128; k++) {
        float wv = __ldg(&w[(size_t)k * 256 + t]);
        acc0 = fmaf(p[0][k], wv, acc0);
        acc1 = fmaf(p[1][k], wv, acc1);
        acc2 = fmaf(p[2][k], wv, acc2);
        acc3 = fmaf(p[3][k], wv, acc3);
    }
    g_fc1[(size_t)(g0 + 0) * 256 + t] = acc0;
    g_fc1[(size_t)(g0 + 1) * 256 + t] = acc1;
    g_fc1[(size_t)(g0 + 2) * 256 + t] = acc2;
    g_fc1[(size_t)(g0 + 3) * 256 + t] = acc3;
}

// ---------------- fc2 ----------------
__global__ void fc2_kernel(const float* __restrict__ w, const float* __restrict__ b,
                           float* __restrict__ out)
{
    int idx = blockIdx.x * blockDim.x + threadIdx.x;
    if (idx >= N_GRAPHS * DOUT) return;
    int g = idx >> 3, o = idx & 7;
    float acc = b[o];
    #pragma unroll 8
    for (int k = 0; k < 256; k++)
        acc = fmaf(g_fc1[(size_t)g * 256 + k], __ldg(&w[k * 8 + o]), acc);
    out[idx] = acc;
}

// ---------------- launch ----------------
extern "C" void kernel_launch(void* const* d_in, const int* in_sizes, int n_in,
                              void* d_out, int out_size)
{
    const float* x = (const float*)d_in[0];
    const void* ei = d_in[1];
    const void* batch = d_in[2];
    const float* Wrel[4]  = {(const float*)d_in[3], (const float*)d_in[6],
                             (const float*)d_in[9], (const float*)d_in[12]};
    const float* Wroot[4] = {(const float*)d_in[4], (const float*)d_in[7],
                             (const float*)d_in[10], (const float*)d_in[13]};
    const float* bias[4]  = {(const float*)d_in[5], (const float*)d_in[8],
                             (const float*)d_in[11], (const float*)d_in[14]};
    const float* fcw = (const float*)d_in[15];
    const float* fcb = (const float*)d_in[16];
    const float* regw = (const float*)d_in[17];
    const float* regb = (const float*)d_in[18];
    float* out = (float*)d_out;

    void* countsPtr = nullptr;
    cudaGetSymbolAddress(&countsPtr, g_counts);
    cudaMemsetAsync(countsPtr, 0, N_NODES * sizeof(int));
    void* gbarPtr = nullptr;
    cudaGetSymbolAddress(&gbarPtr, g_gbar);
    cudaMemsetAsync(gbarPtr, 0, sizeof(unsigned));

    // k1: convert + counts
    convert_count_kernel<<<(N_EDGES + 255) / 256, 256>>>(ei, batch);
    // k2: fused CSR build (scan + fill, software grid barriers)
    csr_build_kernel<<<SCAN_NB, 256>>>();
    // k3: x fp16 mirror
    convert_x16_kernel<<<(N_NODES * (D / 4) + 255) / 256, 256>>>(x);

    const int gatherBlocks = (int)(((long long)N_NODES * 32 + 255) / 256);
    const int gemmBlocks = (N_NODES + 127) / 128;

    int ins[4]  = {0, 1, 2, 1};
    int outs[4] = {1, 2, 1, 2};
    for (int L = 0; L < 4; L++) {
        // k4 on first iteration -> ncu-profiled launch is the gather
        gather_kernel<<<gatherBlocks, 256>>>(ins[L]);
        gemm_fused_kernel<<<gemmBlocks, 256>>>(x, ins[L], outs[L],
                                               Wrel[L], Wroot[L], bias[L]);
    }

    pool_kernel<<<N_GRAPHS, 128>>>(x, 2);
    fc1_kernel<<<N_GRAPHS / 4, 256>>>(fcw, fcb);
    fc2_kernel<<<(N_GRAPHS * DOUT + 127) / 128, 128>>>(regw, regb, out);
}

// round 14
// speedup vs baseline: 1.1691x; 1.1691x over previous
#include <cuda_runtime.h>
#include <cuda_fp16.h>
#include <cstdint>

#define N_NODES 100000
#define N_EDGES 1600000
#define N_GRAPHS 2048
#define D 128
#define DFC 256
#define DOUT 8

#define SCAN_CHUNK 1024
#define SCAN_NB ((N_NODES + SCAN_CHUNK - 1) / SCAN_CHUNK)   // 98

#define SA 20     // A smem stride (floats): banks (20g+t)%32 all distinct
#define SB 136    // B smem stride (floats): banks (8t+g)%32 all distinct

// ---------------- scratch (static device globals; no allocation) ----------------
__device__ float  g_agg[(size_t)N_NODES * D];
__device__ float  g_hA[(size_t)N_NODES * D];
__device__ float  g_hB[(size_t)N_NODES * D];
__device__ __half g_x16[(size_t)N_NODES * D];
__device__ __half g_h16A[(size_t)N_NODES * D];
__device__ __half g_h16B[(size_t)N_NODES * D];
__device__ float  g_pool[(size_t)N_GRAPHS * D];
__device__ float  g_fc1[(size_t)N_GRAPHS * DFC];
__device__ int    g_src[N_EDGES];
__device__ int    g_dst[N_EDGES];
__device__ int    g_batch[N_NODES];
__device__ int    g_counts[N_NODES];          // zeroed by cudaMemsetAsync
__device__ int    g_row_ptr[N_NODES + 1];
__device__ int    g_cursor[N_NODES];
__device__ int    g_csr_src[N_EDGES];
__device__ int    g_blocksum[SCAN_NB];
__device__ unsigned g_gbar;                   // zeroed by cudaMemsetAsync

__device__ __forceinline__ const float* pick_in(const float* x, int sel) {
    return sel == 0 ? x : (sel == 1 ? g_hA : g_hB);
}
__device__ __forceinline__ float* pick_out(int sel) {
    return sel == 1 ? g_hA : g_hB;
}
__device__ __forceinline__ const __half* pick_in16(int sel) {
    return sel == 0 ? g_x16 : (sel == 1 ? g_h16A : g_h16B);
}
__device__ __forceinline__ __half* pick_out16(int sel) {
    return sel == 1 ? g_h16A : g_h16B;
}

// ---------------- tf32 helpers ----------------
__device__ __forceinline__ uint32_t f2tf32(float v) {
    uint32_t r;
    asm("cvt.rna.tf32.f32 %0, %1;" : "=r"(r) : "f"(v));
    return r;
}

__device__ __forceinline__ void mma_tf32(float* c, const uint32_t* a,
                                         uint32_t b0, uint32_t b1) {
    asm("mma.sync.aligned.m16n8k8.row.col.f32.tf32.tf32.f32 "
        "{%0,%1,%2,%3},{%4,%5,%6,%7},{%8,%9},{%0,%1,%2,%3};"
        : "+f"(c[0]), "+f"(c[1]), "+f"(c[2]), "+f"(c[3])
        : "r"(a[0]), "r"(a[1]), "r"(a[2]), "r"(a[3]), "r"(b0), "r"(b1));
}

// ---------------- software grid barrier (blocks co-resident: 98 <= 148 SMs) ----
__device__ __forceinline__ void grid_bar(unsigned target) {
    __syncthreads();
    if (threadIdx.x == 0) {
        __threadfence();
        atomicAdd(&g_gbar, 1u);
        while (*(volatile unsigned*)&g_gbar < target) { }
        __threadfence();
    }
    __syncthreads();
}

// ---------------- convert indices + batch + x fp16 mirror (one kernel) ----------
__device__ __forceinline__ int detect_is64(const void* ei) {
    const long long* p64 = (const long long*)ei;
    int ok = 1;
    #pragma unroll
    for (int i = 0; i < 16; i++) {
        long long v = __ldg(&p64[i]);
        if (v < 0 || v >= N_NODES) ok = 0;
    }
    return ok;
}

__global__ void convert_count_kernel(const void* ei, const void* batch,
                                     const float* __restrict__ x) {
    int i = blockIdx.x * blockDim.x + threadIdx.x;
    int is64 = detect_is64(ei);
    if (i < N_EDGES) {
        int s, d;
        if (is64) {
            const long long* p = (const long long*)ei;
            s = (int)__ldg(&p[i]);
            d = (int)__ldg(&p[(size_t)N_EDGES + i]);
        } else {
            const int* p = (const int*)ei;
            s = __ldg(&p[i]);
            d = __ldg(&p[N_EDGES + i]);
        }
        g_src[i] = s;
        g_dst[i] = d;
        atomicAdd(&g_counts[d], 1);
    }
    if (i < N_NODES) {
        if (is64) g_batch[i] = (int)__ldg(&((const long long*)batch)[i]);
        else      g_batch[i] = __ldg(&((const int*)batch)[i]);
    }
    // x -> fp16 mirror (grid-stride; total threads = 1.6M, elems = 3.2M)
    int nthr = gridDim.x * blockDim.x;
    for (int k = i; k < N_NODES * (D / 4); k += nthr) {
        float4 v = __ldg(reinterpret_cast<const float4*>(x) + k);
        __half2 h0 = __floats2half2_rn(v.x, v.y);
        __half2 h1 = __floats2half2_rn(v.z, v.w);
        uint2 u;
        u.x = *reinterpret_cast<uint32_t*>(&h0);
        u.y = *reinterpret_cast<uint32_t*>(&h1);
        reinterpret_cast<uint2*>(g_x16)[k] = u;
    }
}

// ---------------- fused CSR scan (row_ptr + cursor), software grid barrier ------
__global__ __launch_bounds__(256) void csr_scan_kernel() {
    int b = blockIdx.x, t = threadIdx.x;

    // phase 1: per-chunk totals
    {
        __shared__ int sh[256];
        int i0 = b * SCAN_CHUNK + t * 4;
        int s = 0;
        #pragma unroll
        for (int j = 0; j < 4; j++) {
            int i = i0 + j;
            if (i < N_NODES) s += g_counts[i];
        }
        sh[t] = s;
        __syncthreads();
        for (int off = 128; off > 0; off >>= 1) {
            if (t < off) sh[t] += sh[t + off];
            __syncthreads();
        }
        if (t == 0) g_blocksum[b] = sh[0];
    }

    grid_bar(SCAN_NB);

    // phase 2: redundant scan of chunk sums, then per-chunk exclusive scan
    {
        __shared__ int pre[128];
        int v = (t < SCAN_NB && t < 128) ? g_blocksum[t] : 0;
        if (t < 128) pre[t] = v;
        __syncthreads();
        #pragma unroll
        for (int off = 1; off < 128; off <<= 1) {
            int u = 0;
            if (t < 128 && t >= off) u = pre[t - off];
            __syncthreads();
            if (t < 128) pre[t] += u;
            __syncthreads();
        }
        __shared__ int myblockbase;
        if (t == 0) myblockbase = (b == 0) ? 0 : pre[b - 1];
        __syncthreads();

        __shared__ int sh[256];
        int i0 = b * SCAN_CHUNK + t * 4;
        int c[4];
        int tsum = 0;
        #pragma unroll
        for (int j = 0; j < 4; j++) {
            int i = i0 + j;
            c[j] = (i < N_NODES) ? g_counts[i] : 0;
            tsum += c[j];
        }
        sh[t] = tsum;
        __syncthreads();
        #pragma unroll
        for (int off = 1; off < 256; off <<= 1) {
            int v2 = (t >= off) ? sh[t - off] : 0;
            __syncthreads();
            sh[t] += v2;
            __syncthreads();
        }
        int base = myblockbase + sh[t] - tsum;
        #pragma unroll
        for (int j = 0; j < 4; j++) {
            int i = i0 + j;
            if (i < N_NODES) {
                g_row_ptr[i] = base;
                g_cursor[i]  = base;
                base += c[j];
            }
        }
        if (b == SCAN_NB - 1 && t == 0) g_row_ptr[N_NODES] = N_EDGES;
    }
}

// ---------------- fill CSR (dedicated full-grid kernel) ----------------
__global__ void fill_kernel() {
    int e = blockIdx.x * blockDim.x + threadIdx.x;
    if (e >= N_EDGES) return;
    int d = g_dst[e];
    int pos = atomicAdd(&g_cursor[d], 1);
    g_csr_src[pos] = g_src[e];
}

// ---------------- gather: 32-bit addressing + pairwise hadd2 ----------------
__device__ __forceinline__ void acc_h4(float4& acc, uint2 u) {
    __half2 p0 = *reinterpret_cast<const __half2*>(&u.x);
    __half2 p1 = *reinterpret_cast<const __half2*>(&u.y);
    float2 a = __half22float2(p0);
    float2 b = __half22float2(p1);
    acc.x += a.x; acc.y += a.y; acc.z += b.x; acc.w += b.y;
}

__global__ void gather_kernel(int sel_in) {
    long long idx = (long long)blockIdx.x * blockDim.x + threadIdx.x;
    int node = (int)(idx >> 5);
    if (node >= N_NODES) return;
    int lane = (int)(idx & 31);
    const char* hb = (const char*)pick_in16(sel_in);   // 25.6 MB: 32-bit offsets OK
    uint32_t laneoff = (uint32_t)lane * 8u;
    int beg = g_row_ptr[node];
    int end = g_row_ptr[node + 1];
    int deg = end - beg;

    int myidx = 0;
    if (lane < deg) myidx = __ldg(&g_csr_src[beg + lane]);

    float4 acc = make_float4(0.f, 0.f, 0.f, 0.f);
    int n32 = deg < 32 ? deg : 32;
    int j = 0;

    #pragma unroll 4
    for (; j + 2 <= n32; j += 2) {
        int s0 = __shfl_sync(0xffffffffu, myidx, j);
        int s1 = __shfl_sync(0xffffffffu, myidx, j + 1);
        uint2 u0 = __ldg(reinterpret_cast<const uint2*>(hb + (((uint32_t)s0) << 8) + laneoff));
        uint2 u1 = __ldg(reinterpret_cast<const uint2*>(hb + (((uint32_t)s1) << 8) + laneoff));
        // pairwise fp16 add, then one fp32 accumulate per pair
        __half2 p0 = __hadd2(*reinterpret_cast<const __half2*>(&u0.x),
                             *reinterpret_cast<const __half2*>(&u1.x));
        __half2 p1 = __hadd2(*reinterpret_cast<const __half2*>(&u0.y),
                             *reinterpret_cast<const __half2*>(&u1.y));
        float2 f0 = __half22float2(p0);
        float2 f1 = __half22float2(p1);
        acc.x += f0.x; acc.y += f0.y; acc.z += f1.x; acc.w += f1.y;
    }
    if (j < n32) {                       // odd tail within first 32
        int s = __shfl_sync(0xffffffffu, myidx, j);
        uint2 u = __ldg(reinterpret_cast<const uint2*>(hb + (((uint32_t)s) << 8) + laneoff));
        acc_h4(acc, u);
    }
    for (int e = beg + 32; e < end; e++) {   // rare deg>32 tail
        int s = __ldg(&g_csr_src[e]);
        uint2 u = __ldg(reinterpret_cast<const uint2*>(hb + (((uint32_t)s) << 8) + laneoff));
        acc_h4(acc, u);
    }
    reinterpret_cast<float4*>(g_agg)[(size_t)node * 32 + lane] = acc;
}

// ---------------- fused dual-GEMM via tf32 mma.sync ----------------
__device__ __forceinline__ void mma_pair(
    const uint32_t* __restrict__ As_, const uint32_t* __restrict__ Bs_,
    int kc, int warp_m, int warp_n, int g, int t, float acc[2][8][4])
{
    uint32_t afr[2][4];
    #pragma unroll
    for (int mt = 0; mt < 2; mt++) {
        int r0 = warp_m * 32 + mt * 16;
        afr[mt][0] = As_[(r0 + g) * SA + kc + t];
        afr[mt][1] = As_[(r0 + g + 8) * SA + kc + t];
        afr[mt][2] = As_[(r0 + g) * SA + kc + t + 4];
        afr[mt][3] = As_[(r0 + g + 8) * SA + kc + t + 4];
    }
    #pragma unroll
    for (int nt = 0; nt < 8; nt++) {
        int n0 = warp_n * 64 + nt * 8;
        uint32_t b0 = Bs_[(kc + t) * SB + n0 + g];
        uint32_t b1 = Bs_[(kc + t + 4) * SB + n0 + g];
        mma_tf32(acc[0][nt], afr[0], b0, b1);
        mma_tf32(acc[1][nt], afr[1], b0, b1);
    }
}

__global__ __launch_bounds__(256) void gemm_fused_kernel(
    const float* __restrict__ x, int sel_in, int sel_out,
    const float* __restrict__ Wrel, const float* __restrict__ Wroot,
    const float* __restrict__ bias)
{
    __shared__ uint32_t Aa[128 * SA];
    __shared__ uint32_t Ah[128 * SA];
    __shared__ uint32_t Br[16 * SB];
    __shared__ uint32_t Bo[16 * SB];

    const float* hin = pick_in(x, sel_in);
    float* hout = pick_out(sel_out);
    __half* hout16 = pick_out16(sel_out);

    int m0 = blockIdx.x * 128;
    int tid = threadIdx.x;
    int wid = tid >> 5;
    int lane = tid & 31;
    int warp_m = wid & 3;
    int warp_n = wid >> 2;
    int g = lane >> 2;
    int t = lane & 3;

    float acc[2][8][4];
    #pragma unroll
    for (int mt = 0; mt < 2; mt++)
        #pragma unroll
        for (int nt = 0; nt < 8; nt++)
            #pragma unroll
            for (int j = 0; j < 4; j++) acc[mt][nt][j] = 0.f;

    for (int k0 = 0; k0 < 128; k0 += 16) {
        #pragma unroll
        for (int i = 0; i < 2; i++) {
            int f = tid * 2 + i;
            int row = f >> 2;
            int c4 = f & 3;
            int gr = m0 + row;
            float4 va = make_float4(0.f, 0.f, 0.f, 0.f);
            float4 vh = make_float4(0.f, 0.f, 0.f, 0.f);
            if (gr < N_NODES) {
                va = *reinterpret_cast<const float4*>(g_agg + (size_t)gr * 128 + k0 + c4 * 4);
                vh = *reinterpret_cast<const float4*>(hin   + (size_t)gr * 128 + k0 + c4 * 4);
            }
            int base = row * SA + c4 * 4;
            Aa[base + 0] = f2tf32(va.x); Aa[base + 1] = f2tf32(va.y);
            Aa[base + 2] = f2tf32(va.z); Aa[base + 3] = f2tf32(va.w);
            Ah[base + 0] = f2tf32(vh.x); Ah[base + 1] = f2tf32(vh.y);
            Ah[base + 2] = f2tf32(vh.z); Ah[base + 3] = f2tf32(vh.w);
        }
        #pragma unroll
        for (int i = 0; i < 2; i++) {
            int f = tid * 2 + i;
            int kr = f >> 5;
            int c4 = f & 31;
            float4 vr = *reinterpret_cast<const float4*>(Wrel  + (size_t)(k0 + kr) * 128 + c4 * 4);
            float4 vo = *reinterpret_cast<const float4*>(Wroot + (size_t)(k0 + kr) * 128 + c4 * 4);
            int base = kr * SB + c4 * 4;
            Br[base + 0] = f2tf32(vr.x); Br[base + 1] = f2tf32(vr.y);
            Br[base + 2] = f2tf32(vr.z); Br[base + 3] = f2tf32(vr.w);
            Bo[base + 0] = f2tf32(vo.x); Bo[base + 1] = f2tf32(vo.y);
            Bo[base + 2] = f2tf32(vo.z); Bo[base + 3] = f2tf32(vo.w);
        }
        __syncthreads();

        #pragma unroll
        for (int kc = 0; kc < 16; kc += 8) {
            mma_pair(Aa, Br, kc, warp_m, warp_n, g, t, acc);
            mma_pair(Ah, Bo, kc, warp_m, warp_n, g, t, acc);
        }
        __syncthreads();
    }

    #pragma unroll
    for (int nt = 0; nt < 8; nt++) {
        int col = warp_n * 64 + nt * 8 + 2 * t;
        float b0 = __ldg(&bias[col]);
        float b1 = __ldg(&bias[col + 1]);
        #pragma unroll
        for (int mt = 0; mt < 2; mt++) {
            int row0 = m0 + warp_m * 32 + mt * 16 + g;
            if (row0 < N_NODES) {
                float lo = fmaxf(acc[mt][nt][0] + b0, 0.f);
                float hi = fmaxf(acc[mt][nt][1] + b1, 0.f);
                *reinterpret_cast<float2*>(&hout[(size_t)row0 * 128 + col]) =
                    make_float2(lo, hi);
                *reinterpret_cast<__half2*>(&hout16[(size_t)row0 * 128 + col]) =
                    __floats2half2_rn(lo, hi);
            }
            int row1 = row0 + 8;
            if (row1 < N_NODES) {
                float lo = fmaxf(acc[mt][nt][2] + b0, 0.f);
                float hi = fmaxf(acc[mt][nt][3] + b1, 0.f);
                *reinterpret_cast<float2*>(&hout[(size_t)row1 * 128 + col]) =
                    make_float2(lo, hi);
                *reinterpret_cast<__half2*>(&hout16[(size_t)row1 * 128 + col]) =
                    __floats2half2_rn(lo, hi);
            }
        }
    }
}

// ---------------- pool: sorted-batch segments, block per graph, no atomics ----------------
__device__ __forceinline__ int lower_bound_batch(int v) {
    int lo = 0, hi = N_NODES;
    while (lo < hi) {
        int m = (lo + hi) >> 1;
        if (g_batch[m] < v) lo = m + 1; else hi = m;
    }
    return lo;
}

__global__ __launch_bounds__(128) void pool_kernel(const float* __restrict__ x, int sel_in) {
    int g = blockIdx.x;
    int t = threadIdx.x;
    const float* h = pick_in(x, sel_in);
    int lo = lower_bound_batch(g);
    int hi = lower_bound_batch(g + 1);
    float acc = 0.f;
    for (int n = lo; n < hi; n++)
        acc += __ldg(&h[(size_t)n * 128 + t]);
    float cnt = (float)(hi - lo);
    g_pool[(size_t)g * 128 + t] = acc / fmaxf(cnt, 1.0f);
}

// ---------------- fc1: 4 graphs per block ----------------
__global__ __launch_bounds__(256) void fc1_kernel(
    const float* __restrict__ w, const float* __restrict__ b)
{
    __shared__ float p[4][128];
    int g0 = blockIdx.x * 4;
    int t = threadIdx.x;
    #pragma unroll
    for (int i = 0; i < 2; i++) {
        int f = t + i * 256;
        p[f >> 7][f & 127] = g_pool[(size_t)g0 * 128 + f];
    }
    __syncthreads();
    float acc0 = b[t], acc1 = b[t], acc2 = b[t], acc3 = b[t];
    #pragma unroll 4
    for (int k = 0; k < 128; k++) {
        float wv = __ldg(&w[(size_t)k * 256 + t]);
        acc0 = fmaf(p[0][k], wv, acc0);
        acc1 = fmaf(p[1][k], wv, acc1);
        acc2 = fmaf(p[2][k], wv, acc2);
        acc3 = fmaf(p[3][k], wv, acc3);
    }
    g_fc1[(size_t)(g0 + 0) * 256 + t] = acc0;
    g_fc1[(size_t)(g0 + 1) * 256 + t] = acc1;
    g_fc1[(size_t)(g0 + 2) * 256 + t] = acc2;
    g_fc1[(size_t)(g0 + 3) * 256 + t] = acc3;
}

// ---------------- fc2 ----------------
__global__ void fc2_kernel(const float* __restrict__ w, const float* __restrict__ b,
                           float* __restrict__ out)
{
    int idx = blockIdx.x * blockDim.x + threadIdx.x;
    if (idx >= N_GRAPHS * DOUT) return;
    int g = idx >> 3, o = idx & 7;
    float acc = b[o];
    #pragma unroll 8
    for (int k = 0; k < 256; k++)
        acc = fmaf(g_fc1[(size_t)g * 256 + k], __ldg(&w[k * 8 + o]), acc);
    out[idx] = acc;
}

// ---------------- launch ----------------
extern "C" void kernel_launch(void* const* d_in, const int* in_sizes, int n_in,
                              void* d_out, int out_size)
{
    const float* x = (const float*)d_in[0];
    const void* ei = d_in[1];
    const void* batch = d_in[2];
    const float* Wrel[4]  = {(const float*)d_in[3], (const float*)d_in[6],
                             (const float*)d_in[9], (const float*)d_in[12]};
    const float* Wroot[4] = {(const float*)d_in[4], (const float*)d_in[7],
                             (const float*)d_in[10], (const float*)d_in[13]};
    const float* bias[4]  = {(const float*)d_in[5], (const float*)d_in[8],
                             (const float*)d_in[11], (const float*)d_in[14]};
    const float* fcw = (const float*)d_in[15];
    const float* fcb = (const float*)d_in[16];
    const float* regw = (const float*)d_in[17];
    const float* regb = (const float*)d_in[18];
    float* out = (float*)d_out;

    void* countsPtr = nullptr;
    cudaGetSymbolAddress(&countsPtr, g_counts);
    cudaMemsetAsync(countsPtr, 0, N_NODES * sizeof(int));
    void* gbarPtr = nullptr;
    cudaGetSymbolAddress(&gbarPtr, g_gbar);
    cudaMemsetAsync(gbarPtr, 0, sizeof(unsigned));

    // k1: convert indices + batch + x16 mirror
    convert_count_kernel<<<(N_EDGES + 255) / 256, 256>>>(ei, batch, x);
    // k2: fused CSR scan
    csr_scan_kernel<<<SCAN_NB, 256>>>();
    // k3: fill (full grid)
    fill_kernel<<<(N_EDGES + 255) / 256, 256>>>();

    const int gatherBlocks = (int)(((long long)N_NODES * 32 + 255) / 256);
    const int gemmBlocks = (N_NODES + 127) / 128;

    int ins[4]  = {0, 1, 2, 1};
    int outs[4] = {1, 2, 1, 2};
    for (int L = 0; L < 4; L++) {
        // k4 on first iteration -> profiled launch is the new gather
        gather_kernel<<<gatherBlocks, 256>>>(ins[L]);
        gemm_fused_kernel<<<gemmBlocks, 256>>>(x, ins[L], outs[L],
                                               Wrel[L], Wroot[L], bias[L]);
    }

    pool_kernel<<<N_GRAPHS, 128>>>(x, 2);
    fc1_kernel<<<N_GRAPHS / 4, 256>>>(fcw, fcb);
    fc2_kernel<<<(N_GRAPHS * DOUT + 127) / 128, 128>>>(regw, regb, out);
}